// round 1
// baseline (speedup 1.0000x reference)
#include <cuda_runtime.h>
#include <math.h>
#include <stdint.h>

#define B  4
#define NN 65536
#define KK 16
#define DD 32
#define NP 16384

// scratch: transposed features [b][n][d]
__device__ float g_pool_t[(size_t)B * NN * DD];    // 33.6 MB
__device__ float g_interp_t[(size_t)B * NP * DD];  //  8.4 MB

// -------- transpose [B, 32, M] -> [B, M, 32] --------
__global__ void transpose_kernel(const float* __restrict__ in, float* __restrict__ out, int M) {
    __shared__ float tile[32][33];
    int b  = blockIdx.y;
    int m0 = blockIdx.x * 32;
    int tx = threadIdx.x;        // 0..31
    int ty = threadIdx.y;        // 0..7
#pragma unroll
    for (int r = 0; r < 4; r++) {
        int d = ty + 8 * r;
        tile[d][tx] = in[((size_t)b * DD + d) * M + m0 + tx];
    }
    __syncthreads();
#pragma unroll
    for (int r = 0; r < 4; r++) {
        int m = ty + 8 * r;
        out[((size_t)b * M + m0 + m) * DD + tx] = tile[tx][m];
    }
}

// -------- relative position encoding: out [B,N,K,10] --------
__global__ void rel_kernel(const float* __restrict__ xyz,
                           const int*   __restrict__ nidx,
                           float* __restrict__ out) {
    int gid = blockIdx.x * blockDim.x + threadIdx.x;   // b*N*K + n*K + k
    if (gid >= B * NN * KK) return;
    int b  = gid / (NN * KK);
    int nk = gid - b * (NN * KK);
    int n  = nk / KK;

    int i = nidx[gid];

    const float* p = xyz + ((size_t)b * NN + n) * 3;
    float x = p[0], y = p[1], z = p[2];
    const float* q = xyz + ((size_t)b * NN + i) * 3;
    float nx = q[0], ny = q[1], nz = q[2];

    float rx = x - nx, ry = y - ny, rz = z - nz;
    float dist = sqrtf(rx * rx + ry * ry + rz * rz);

    float2* o = (float2*)(out + (size_t)gid * 10);
    o[0] = make_float2(dist, rx);
    o[1] = make_float2(ry, rz);
    o[2] = make_float2(x, y);
    o[3] = make_float2(z, nx);
    o[4] = make_float2(ny, nz);
}

// -------- gather-max pooling: out [B,32,Np] --------
// block = 256 threads (8 warps), handles a tile of 32 np x 32 d
__global__ void pool_kernel(const int* __restrict__ pool_idx, float* __restrict__ out) {
    __shared__ float tile[32][33];
    int b   = blockIdx.y;
    int np0 = blockIdx.x * 32;
    int lane = threadIdx.x & 31;
    int w    = threadIdx.x >> 5;   // 0..7

#pragma unroll
    for (int r = 0; r < 4; r++) {
        int npl = w + 8 * r;                   // local np 0..31
        const int* idx = pool_idx + ((size_t)b * NP + np0 + npl) * KK;
        float m = -INFINITY;
#pragma unroll
        for (int k = 0; k < KK; k++) {
            int i = idx[k];                    // uniform across warp
            float v = g_pool_t[((size_t)b * NN + i) * DD + lane];  // coalesced 128B
            m = fmaxf(m, v);
        }
        tile[npl][lane] = m;
    }
    __syncthreads();
    // write: warp = 32 consecutive np, fixed d -> coalesced
#pragma unroll
    for (int r = 0; r < 4; r++) {
        int d = w + 8 * r;
        out[((size_t)b * DD + d) * NP + np0 + lane] = tile[lane][d];
    }
}

// -------- nearest interpolation: out [B,32,N] --------
// block = 256 threads, tile of 32 u x 32 d
__global__ void interp_kernel(const int* __restrict__ interp_idx, float* __restrict__ out) {
    __shared__ float tile[32][33];
    int b  = blockIdx.y;
    int u0 = blockIdx.x * 32;
    int lane = threadIdx.x & 31;
    int w    = threadIdx.x >> 5;

#pragma unroll
    for (int r = 0; r < 4; r++) {
        int ul = w + 8 * r;
        int i  = interp_idx[(size_t)b * NN + u0 + ul];  // uniform across warp
        tile[ul][lane] = g_interp_t[((size_t)b * NP + i) * DD + lane];  // coalesced
    }
    __syncthreads();
#pragma unroll
    for (int r = 0; r < 4; r++) {
        int d = w + 8 * r;
        out[((size_t)b * DD + d) * NN + u0 + lane] = tile[lane][d];
    }
}

extern "C" void kernel_launch(void* const* d_in, const int* in_sizes, int n_in,
                              void* d_out, int out_size) {
    const float* xyz         = (const float*)d_in[0];   // [B,N,3]
    const int*   neigh_idx   = (const int*)  d_in[1];   // [B,N,K]
    const float* feat_pool   = (const float*)d_in[2];   // [B,32,N,1]
    const int*   pool_idx    = (const int*)  d_in[3];   // [B,Np,K]
    const float* feat_interp = (const float*)d_in[4];   // [B,32,Np,1]
    const int*   interp_idx  = (const int*)  d_in[5];   // [B,N,1]

    float* out = (float*)d_out;
    float* out_rel    = out;                                          // B*N*K*10
    float* out_pool   = out + (size_t)B * NN * KK * 10;               // B*32*Np
    float* out_interp = out_pool + (size_t)B * DD * NP;               // B*32*N

    float* pool_t;   cudaGetSymbolAddress((void**)&pool_t,   g_pool_t);
    float* interp_t; cudaGetSymbolAddress((void**)&interp_t, g_interp_t);

    // transposes
    {
        dim3 blk(32, 8);
        dim3 g1(NN / 32, B);
        transpose_kernel<<<g1, blk>>>(feat_pool, pool_t, NN);
        dim3 g2(NP / 32, B);
        transpose_kernel<<<g2, blk>>>(feat_interp, interp_t, NP);
    }

    // relative pos encoding
    {
        int total = B * NN * KK;
        rel_kernel<<<(total + 255) / 256, 256>>>(xyz, neigh_idx, out_rel);
    }

    // pooling (needs pool_t)
    {
        dim3 g(NP / 32, B);
        pool_kernel<<<g, 256>>>(pool_idx, out_pool);
    }

    // interpolation (needs interp_t)
    {
        dim3 g(NN / 32, B);
        interp_kernel<<<g, 256>>>(interp_idx, out_interp);
    }
}

// round 2
// speedup vs baseline: 1.6423x; 1.6423x over previous
#include <cuda_runtime.h>
#include <math.h>

#define B  4
#define NN 65536
#define KK 16
#define DD 32
#define NP 16384

// scratch: transposed features [b][n][d]
__device__ float g_pool_t[(size_t)B * NN * DD];    // 33.6 MB
__device__ float g_interp_t[(size_t)B * NP * DD];  //  8.4 MB

#define TB1 (B * (NN / 32))        // 8192  transpose feat_pool
#define TB2 (B * (NP / 32))        // 2048  transpose feat_interp
#define RB  (B * NN * KK / 256)    // 16384 rel blocks

// ============ Kernel A: transposes + relative-pos-encoding (independent) ============
__global__ void __launch_bounds__(256) kernelA(
    const float* __restrict__ feat_pool,
    const float* __restrict__ feat_interp,
    const float* __restrict__ xyz,
    const int*   __restrict__ nidx,
    float* __restrict__ out_rel)
{
    int bid = blockIdx.x;
    int tid = threadIdx.x;

    if (bid < TB1 + TB2) {
        // -------- transpose [B,32,M] -> [B,M,32] --------
        __shared__ float tile[32][33];
        const float* in;
        float* outp;
        int M, tb;
        if (bid < TB1) { in = feat_pool;   outp = g_pool_t;   M = NN; tb = bid; }
        else           { in = feat_interp; outp = g_interp_t; M = NP; tb = bid - TB1; }
        int mb = M / 32;
        int b  = tb / mb;
        int m0 = (tb - b * mb) * 32;
        int tx = tid & 31, ty = tid >> 5;
#pragma unroll
        for (int r = 0; r < 4; r++) {
            int d = ty + 8 * r;
            tile[d][tx] = in[((size_t)(b * DD + d)) * M + m0 + tx];
        }
        __syncthreads();
#pragma unroll
        for (int r = 0; r < 4; r++) {
            int m = ty + 8 * r;
            outp[((size_t)(b * M + m0 + m)) * DD + tx] = tile[tx][m];
        }
    } else {
        // -------- rel: out [B,N,K,10], smem-staged float4 stores --------
        __shared__ float s[2560];
        int rb   = bid - (TB1 + TB2);
        int pair = rb * 256 + tid;          // b*N*K + n*K + k
        int b  = pair >> 20;                // N*K = 2^20
        int nk = pair & 0xFFFFF;
        int n  = nk >> 4;
        int i  = __ldg(&nidx[pair]);

        const float* p = xyz + ((size_t)((b << 16) + n)) * 3;
        float x  = __ldg(p),     y  = __ldg(p + 1), z  = __ldg(p + 2);
        const float* q = xyz + ((size_t)((b << 16) + i)) * 3;
        float nx = __ldg(q),     ny = __ldg(q + 1), nz = __ldg(q + 2);

        float rx = x - nx, ry = y - ny, rz = z - nz;
        float dist = sqrtf(rx * rx + ry * ry + rz * rz);

        float* sp = s + tid * 10;
        sp[0] = dist; sp[1] = rx; sp[2] = ry; sp[3] = rz;
        sp[4] = x;    sp[5] = y;  sp[6] = z;
        sp[7] = nx;   sp[8] = ny; sp[9] = nz;
        __syncthreads();

        float4* o4       = (float4*)(out_rel + (size_t)rb * 2560);
        const float4* s4 = (const float4*)s;
        o4[tid]       = s4[tid];
        o4[256 + tid] = s4[256 + tid];
        if (tid < 128) o4[512 + tid] = s4[512 + tid];
    }
}

// ============ Kernel B: pool + interp (both read transposed scratch) ============
#define PB (B * (NP / 32))   // 2048
#define IB (B * (NN / 32))   // 8192

__global__ void __launch_bounds__(256) kernelB(
    const int* __restrict__ pool_idx,
    const int* __restrict__ interp_idx,
    float* __restrict__ out_pool,
    float* __restrict__ out_interp)
{
    __shared__ float tile[32][33];
    int bid  = blockIdx.x;
    int tid  = threadIdx.x;
    int lane = tid & 31, w = tid >> 5;
    int row  = w * 4 + (lane >> 3);   // 0..31 local row (np or u)
    int dv   = lane & 7;              // float4 lane within d=32

    if (bid < PB) {
        // -------- gather-max pooling --------
        int b   = bid / (NP / 32);
        int np0 = (bid - b * (NP / 32)) * 32;
        const int* ip = pool_idx + (b * NP + np0 + row) * KK;
        const float* basep = g_pool_t + (size_t)b * NN * DD;

        float4 m = make_float4(-INFINITY, -INFINITY, -INFINITY, -INFINITY);
#pragma unroll
        for (int kc = 0; kc < 4; kc++) {
            int4 q = __ldg((const int4*)ip + kc);
            int qq[4] = {q.x, q.y, q.z, q.w};
#pragma unroll
            for (int j = 0; j < 4; j++) {
                float4 v = *(const float4*)(basep + qq[j] * DD + dv * 4);
                m.x = fmaxf(m.x, v.x); m.y = fmaxf(m.y, v.y);
                m.z = fmaxf(m.z, v.z); m.w = fmaxf(m.w, v.w);
            }
        }
        tile[row][dv * 4 + 0] = m.x;
        tile[row][dv * 4 + 1] = m.y;
        tile[row][dv * 4 + 2] = m.z;
        tile[row][dv * 4 + 3] = m.w;
        __syncthreads();
#pragma unroll
        for (int r = 0; r < 4; r++) {
            int d = w + 8 * r;
            out_pool[(size_t)(b * DD + d) * NP + np0 + lane] = tile[lane][d];
        }
    } else {
        // -------- nearest interpolation --------
        int ib = bid - PB;
        int b  = ib / (NN / 32);
        int u0 = (ib - b * (NN / 32)) * 32;
        int i  = __ldg(&interp_idx[b * NN + u0 + row]);   // broadcast per 8 lanes
        float4 v = *(const float4*)(g_interp_t + ((size_t)(b * NP + i)) * DD + dv * 4);
        tile[row][dv * 4 + 0] = v.x;
        tile[row][dv * 4 + 1] = v.y;
        tile[row][dv * 4 + 2] = v.z;
        tile[row][dv * 4 + 3] = v.w;
        __syncthreads();
#pragma unroll
        for (int r = 0; r < 4; r++) {
            int d = w + 8 * r;
            out_interp[(size_t)(b * DD + d) * NN + u0 + lane] = tile[lane][d];
        }
    }
}

extern "C" void kernel_launch(void* const* d_in, const int* in_sizes, int n_in,
                              void* d_out, int out_size) {
    const float* xyz         = (const float*)d_in[0];   // [B,N,3]
    const int*   neigh_idx   = (const int*)  d_in[1];   // [B,N,K]
    const float* feat_pool   = (const float*)d_in[2];   // [B,32,N,1]
    const int*   pool_idx    = (const int*)  d_in[3];   // [B,Np,K]
    const float* feat_interp = (const float*)d_in[4];   // [B,32,Np,1]
    const int*   interp_idx  = (const int*)  d_in[5];   // [B,N,1]

    float* out = (float*)d_out;
    float* out_rel    = out;                                // B*N*K*10
    float* out_pool   = out + (size_t)B * NN * KK * 10;     // B*32*Np
    float* out_interp = out_pool + (size_t)B * DD * NP;     // B*32*N

    kernelA<<<TB1 + TB2 + RB, 256>>>(feat_pool, feat_interp, xyz, neigh_idx, out_rel);
    kernelB<<<PB + IB, 256>>>(pool_idx, interp_idx, out_pool, out_interp);
}

// round 3
// speedup vs baseline: 1.7220x; 1.0485x over previous
#include <cuda_runtime.h>
#include <math.h>

#define B  4
#define NN 65536
#define KK 16
#define DD 32
#define NP 16384

// scratch: transposed features [b][n][d]
__device__ float g_pool_t[(size_t)B * NN * DD];    // 33.6 MB
__device__ float g_interp_t[(size_t)B * NP * DD];  //  8.4 MB

#define TB1 (B * (NN / 32))        // 8192  transpose feat_pool tiles
#define TB2 (B * (NP / 32))        // 2048  transpose feat_interp tiles
#define RELB (B * NN * KK / 256)   // 16384 rel blocks
#define PB  (B * (NP / 32))        // 2048 pool blocks
#define IB4 (B * (NN / 128))       // 2048 interp blocks (4 tiles each)
#define K2B (RELB + PB + IB4)      // 20480, dispatched bid%10

// ============ K1: transposes [B,32,M] -> [B,M,32] ============
__global__ void __launch_bounds__(256) kernelT(
    const float* __restrict__ feat_pool,
    const float* __restrict__ feat_interp)
{
    __shared__ float tile[32][33];
    int bid = blockIdx.x;
    const float* in;
    float* outp;
    int M, tb;
    if (bid < TB1) { in = feat_pool;   outp = g_pool_t;   M = NN; tb = bid; }
    else           { in = feat_interp; outp = g_interp_t; M = NP; tb = bid - TB1; }
    int mb = M / 32;
    int b  = tb / mb;
    int m0 = (tb - b * mb) * 32;
    int tx = threadIdx.x & 31, ty = threadIdx.x >> 5;
#pragma unroll
    for (int r = 0; r < 4; r++) {
        int d = ty + 8 * r;
        tile[d][tx] = __ldcs(&in[((size_t)(b * DD + d)) * M + m0 + tx]);
    }
    __syncthreads();
#pragma unroll
    for (int r = 0; r < 4; r++) {
        int m = ty + 8 * r;
        outp[((size_t)(b * M + m0 + m)) * DD + tx] = tile[tx][m];
    }
}

// ============ K2: rel + pool + interp, interleaved ============
__global__ void __launch_bounds__(256) kernelF(
    const float* __restrict__ xyz,
    const int*   __restrict__ nidx,
    const int*   __restrict__ pool_idx,
    const int*   __restrict__ interp_idx,
    float* __restrict__ out_rel,
    float* __restrict__ out_pool,
    float* __restrict__ out_interp)
{
    __shared__ float smem[4 * 32 * 33];   // 16.9 KB, used differently per role
    int bid = blockIdx.x;
    int tid = threadIdx.x;
    int r = bid % 10;
    int g = bid / 10;

    if (r == 0) {
        // -------- gather-max pooling: block g handles one 32-np tile --------
        float (*tile)[33] = (float (*)[33])smem;
        int lane = tid & 31, w = tid >> 5;
        int row  = w * 4 + (lane >> 3);
        int dv   = lane & 7;
        int b   = g / (NP / 32);
        int np0 = (g - b * (NP / 32)) * 32;
        const int* ip = pool_idx + (b * NP + np0 + row) * KK;
        const float* basep = g_pool_t + (size_t)b * NN * DD;

        float4 m = make_float4(-INFINITY, -INFINITY, -INFINITY, -INFINITY);
#pragma unroll
        for (int kc = 0; kc < 4; kc++) {
            int4 q = __ldcs((const int4*)ip + kc);
            int qq[4] = {q.x, q.y, q.z, q.w};
#pragma unroll
            for (int j = 0; j < 4; j++) {
                float4 v = *(const float4*)(basep + qq[j] * DD + dv * 4);
                m.x = fmaxf(m.x, v.x); m.y = fmaxf(m.y, v.y);
                m.z = fmaxf(m.z, v.z); m.w = fmaxf(m.w, v.w);
            }
        }
        tile[row][dv * 4 + 0] = m.x;
        tile[row][dv * 4 + 1] = m.y;
        tile[row][dv * 4 + 2] = m.z;
        tile[row][dv * 4 + 3] = m.w;
        __syncthreads();
#pragma unroll
        for (int rr = 0; rr < 4; rr++) {
            int d = w + 8 * rr;
            __stcs(&out_pool[(size_t)(b * DD + d) * NP + np0 + lane], tile[lane][d]);
        }
    } else if (r == 5) {
        // -------- nearest interpolation: block g handles 4 consecutive 32-u tiles --------
        float (*tile)[33] = (float (*)[33])smem;  // [4*32][33]
        int lane = tid & 31, w = tid >> 5;
        int row  = w * 4 + (lane >> 3);
        int dv   = lane & 7;
        int b  = g / (NN / 128);
        int u0 = (g - b * (NN / 128)) * 128;

        float4 v[4];
#pragma unroll
        for (int it = 0; it < 4; it++) {
            int i = __ldg(&interp_idx[b * NN + u0 + it * 32 + row]);
            v[it] = *(const float4*)(g_interp_t + ((size_t)(b * NP + i)) * DD + dv * 4);
        }
#pragma unroll
        for (int it = 0; it < 4; it++) {
            tile[it * 32 + row][dv * 4 + 0] = v[it].x;
            tile[it * 32 + row][dv * 4 + 1] = v[it].y;
            tile[it * 32 + row][dv * 4 + 2] = v[it].z;
            tile[it * 32 + row][dv * 4 + 3] = v[it].w;
        }
        __syncthreads();
#pragma unroll
        for (int it = 0; it < 4; it++) {
#pragma unroll
            for (int rr = 0; rr < 4; rr++) {
                int d = w + 8 * rr;
                __stcs(&out_interp[(size_t)(b * DD + d) * NN + u0 + it * 32 + lane],
                       tile[it * 32 + lane][d]);
            }
        }
    } else {
        // -------- rel: out [B,N,K,10], smem-staged float4 streaming stores --------
        float* s = smem;
        int rb = bid - 2 * g - 1 - (r > 5);   // rel block id 0..16383
        int pair = rb * 256 + tid;            // b*N*K + n*K + k
        int b  = pair >> 20;                  // N*K = 2^20
        int nk = pair & 0xFFFFF;
        int n  = nk >> 4;
        int i  = __ldcs(&nidx[pair]);

        const float* p = xyz + ((size_t)((b << 16) + n)) * 3;
        float x  = __ldg(p),     y  = __ldg(p + 1), z  = __ldg(p + 2);
        const float* q = xyz + ((size_t)((b << 16) + i)) * 3;
        float nx = __ldg(q),     ny = __ldg(q + 1), nz = __ldg(q + 2);

        float rx = x - nx, ry = y - ny, rz = z - nz;
        float dist = sqrtf(rx * rx + ry * ry + rz * rz);

        float* sp = s + tid * 10;
        sp[0] = dist; sp[1] = rx; sp[2] = ry; sp[3] = rz;
        sp[4] = x;    sp[5] = y;  sp[6] = z;
        sp[7] = nx;   sp[8] = ny; sp[9] = nz;
        __syncthreads();

        float4* o4       = (float4*)(out_rel + (size_t)rb * 2560);
        const float4* s4 = (const float4*)s;
        __stcs(&o4[tid],       s4[tid]);
        __stcs(&o4[256 + tid], s4[256 + tid]);
        if (tid < 128) __stcs(&o4[512 + tid], s4[512 + tid]);
    }
}

extern "C" void kernel_launch(void* const* d_in, const int* in_sizes, int n_in,
                              void* d_out, int out_size) {
    const float* xyz         = (const float*)d_in[0];   // [B,N,3]
    const int*   neigh_idx   = (const int*)  d_in[1];   // [B,N,K]
    const float* feat_pool   = (const float*)d_in[2];   // [B,32,N,1]
    const int*   pool_idx    = (const int*)  d_in[3];   // [B,Np,K]
    const float* feat_interp = (const float*)d_in[4];   // [B,32,Np,1]
    const int*   interp_idx  = (const int*)  d_in[5];   // [B,N,1]

    float* out = (float*)d_out;
    float* out_rel    = out;                                // B*N*K*10
    float* out_pool   = out + (size_t)B * NN * KK * 10;     // B*32*Np
    float* out_interp = out_pool + (size_t)B * DD * NP;     // B*32*N

    kernelT<<<TB1 + TB2, 256>>>(feat_pool, feat_interp);
    kernelF<<<K2B, 256>>>(xyz, neigh_idx, pool_idx, interp_idx,
                          out_rel, out_pool, out_interp);
}

// round 4
// speedup vs baseline: 1.8646x; 1.0829x over previous
#include <cuda_runtime.h>
#include <math.h>

#define B  4
#define NN 65536
#define KK 16
#define DD 32
#define NP 16384

// scratch
__device__ float  g_pool_t[(size_t)B * NN * DD];    // 33.6 MB  [b][n][d]
__device__ float  g_interp_t[(size_t)B * NP * DD];  //  8.4 MB  [b][np][d]
__device__ float4 g_xyz4[(size_t)B * NN];           //  4.2 MB  padded xyz

#define TB1 (B * (NN / 32))        // 8192  transpose feat_pool tiles
#define TB2 (B * (NP / 32))        // 2048  transpose feat_interp tiles
#define XB  (B * NN / 256)         // 1024  xyz padding blocks
#define RELB (B * NN * KK / 256)   // 16384 rel blocks
#define PB  (B * (NP / 32))        // 2048 pool blocks
#define IB4 (B * (NN / 128))       // 2048 interp blocks (4 tiles each)
#define K2B (RELB + PB + IB4)      // 20480, dispatched bid%10

// ============ K1: transposes + xyz padding ============
__global__ void __launch_bounds__(256) kernelT(
    const float* __restrict__ feat_pool,
    const float* __restrict__ feat_interp,
    const float* __restrict__ xyz)
{
    __shared__ float sm[32 * 33];
    int bid = blockIdx.x;
    int tid = threadIdx.x;

    if (bid < TB1 + TB2) {
        float (*tile)[33] = (float (*)[33])sm;
        const float* in;
        float* outp;
        int M, tb;
        if (bid < TB1) { in = feat_pool;   outp = g_pool_t;   M = NN; tb = bid; }
        else           { in = feat_interp; outp = g_interp_t; M = NP; tb = bid - TB1; }
        int mb = M / 32;
        int b  = tb / mb;
        int m0 = (tb - b * mb) * 32;
        int tx = tid & 31, ty = tid >> 5;
#pragma unroll
        for (int r = 0; r < 4; r++) {
            int d = ty + 8 * r;
            tile[d][tx] = __ldcs(&in[((size_t)(b * DD + d)) * M + m0 + tx]);
        }
        __syncthreads();
#pragma unroll
        for (int r = 0; r < 4; r++) {
            int m = ty + 8 * r;
            outp[((size_t)(b * M + m0 + m)) * DD + tx] = tile[tx][m];
        }
    } else {
        // pad xyz [B*N,3] -> [B*N] float4 (256 points per block)
        float* s = sm;   // 768 floats
        int p0 = (bid - TB1 - TB2) * 256;   // first point
        const float* src = xyz + (size_t)p0 * 3;
        s[tid]       = __ldcs(&src[tid]);
        s[256 + tid] = __ldcs(&src[256 + tid]);
        s[512 + tid] = __ldcs(&src[512 + tid]);
        __syncthreads();
        g_xyz4[p0 + tid] = make_float4(s[tid * 3], s[tid * 3 + 1], s[tid * 3 + 2], 0.0f);
    }
}

// ============ K2: rel + pool + interp, interleaved ============
__global__ void __launch_bounds__(256) kernelF(
    const int* __restrict__ nidx,
    const int* __restrict__ pool_idx,
    const int* __restrict__ interp_idx,
    float* __restrict__ out_rel,
    float* __restrict__ out_pool,
    float* __restrict__ out_interp)
{
    __shared__ float smem[4 * 32 * 33];   // 16.9 KB
    int bid = blockIdx.x;
    int tid = threadIdx.x;
    int r = bid % 10;
    int g = bid / 10;

    if (r == 0) {
        // -------- gather-max pooling --------
        float (*tile)[33] = (float (*)[33])smem;
        int lane = tid & 31, w = tid >> 5;
        int row  = w * 4 + (lane >> 3);
        int dv   = lane & 7;
        int b   = g / (NP / 32);
        int np0 = (g - b * (NP / 32)) * 32;
        const int* ip = pool_idx + (b * NP + np0 + row) * KK;
        const float* basep = g_pool_t + (size_t)b * NN * DD;

        float4 m = make_float4(-INFINITY, -INFINITY, -INFINITY, -INFINITY);
#pragma unroll
        for (int kc = 0; kc < 4; kc++) {
            int4 q = __ldcs((const int4*)ip + kc);
            int qq[4] = {q.x, q.y, q.z, q.w};
#pragma unroll
            for (int j = 0; j < 4; j++) {
                float4 v = *(const float4*)(basep + qq[j] * DD + dv * 4);
                m.x = fmaxf(m.x, v.x); m.y = fmaxf(m.y, v.y);
                m.z = fmaxf(m.z, v.z); m.w = fmaxf(m.w, v.w);
            }
        }
        tile[row][dv * 4 + 0] = m.x;
        tile[row][dv * 4 + 1] = m.y;
        tile[row][dv * 4 + 2] = m.z;
        tile[row][dv * 4 + 3] = m.w;
        __syncthreads();
#pragma unroll
        for (int rr = 0; rr < 4; rr++) {
            int d = w + 8 * rr;
            __stcs(&out_pool[(size_t)(b * DD + d) * NP + np0 + lane], tile[lane][d]);
        }
    } else if (r == 5) {
        // -------- nearest interpolation: 4 tiles / block --------
        float (*tile)[33] = (float (*)[33])smem;
        int lane = tid & 31, w = tid >> 5;
        int row  = w * 4 + (lane >> 3);
        int dv   = lane & 7;
        int b  = g / (NN / 128);
        int u0 = (g - b * (NN / 128)) * 128;

        float4 v[4];
#pragma unroll
        for (int it = 0; it < 4; it++) {
            int i = __ldg(&interp_idx[b * NN + u0 + it * 32 + row]);
            v[it] = *(const float4*)(g_interp_t + ((size_t)(b * NP + i)) * DD + dv * 4);
        }
#pragma unroll
        for (int it = 0; it < 4; it++) {
            tile[it * 32 + row][dv * 4 + 0] = v[it].x;
            tile[it * 32 + row][dv * 4 + 1] = v[it].y;
            tile[it * 32 + row][dv * 4 + 2] = v[it].z;
            tile[it * 32 + row][dv * 4 + 3] = v[it].w;
        }
        __syncthreads();
#pragma unroll
        for (int it = 0; it < 4; it++) {
#pragma unroll
            for (int rr = 0; rr < 4; rr++) {
                int d = w + 8 * rr;
                __stcs(&out_interp[(size_t)(b * DD + d) * NN + u0 + it * 32 + lane],
                       tile[it * 32 + lane][d]);
            }
        }
    } else {
        // -------- rel: out [B,N,K,10] --------
        float* s = smem;
        int rb = bid - 2 * g - 1 - (r > 5);   // rel block id 0..16383
        int pair = rb * 256 + tid;            // b*N*K + n*K + k
        int b  = pair >> 20;
        int nk = pair & 0xFFFFF;
        int n  = nk >> 4;
        int i  = __ldcs(&nidx[pair]);

        float4 P = __ldg(&g_xyz4[(b << 16) + n]);   // broadcast across 16 lanes
        float4 Q = __ldg(&g_xyz4[(b << 16) + i]);   // scattered, 1 LDG.128

        float rx = P.x - Q.x, ry = P.y - Q.y, rz = P.z - Q.z;
        float dist = sqrtf(rx * rx + ry * ry + rz * rz);

        float2* sp = (float2*)(s + tid * 10);
        sp[0] = make_float2(dist, rx);
        sp[1] = make_float2(ry, rz);
        sp[2] = make_float2(P.x, P.y);
        sp[3] = make_float2(P.z, Q.x);
        sp[4] = make_float2(Q.y, Q.z);
        __syncthreads();

        float4* o4       = (float4*)(out_rel + (size_t)rb * 2560);
        const float4* s4 = (const float4*)s;
        __stcs(&o4[tid],       s4[tid]);
        __stcs(&o4[256 + tid], s4[256 + tid]);
        if (tid < 128) __stcs(&o4[512 + tid], s4[512 + tid]);
    }
}

extern "C" void kernel_launch(void* const* d_in, const int* in_sizes, int n_in,
                              void* d_out, int out_size) {
    const float* xyz         = (const float*)d_in[0];   // [B,N,3]
    const int*   neigh_idx   = (const int*)  d_in[1];   // [B,N,K]
    const float* feat_pool   = (const float*)d_in[2];   // [B,32,N,1]
    const int*   pool_idx    = (const int*)  d_in[3];   // [B,Np,K]
    const float* feat_interp = (const float*)d_in[4];   // [B,32,Np,1]
    const int*   interp_idx  = (const int*)  d_in[5];   // [B,N,1]

    float* out = (float*)d_out;
    float* out_rel    = out;                                // B*N*K*10
    float* out_pool   = out + (size_t)B * NN * KK * 10;     // B*32*Np
    float* out_interp = out_pool + (size_t)B * DD * NP;     // B*32*N

    kernelT<<<TB1 + TB2 + XB, 256>>>(feat_pool, feat_interp, xyz);
    kernelF<<<K2B, 256>>>(neigh_idx, pool_idx, interp_idx,
                          out_rel, out_pool, out_interp);
}

// round 5
// speedup vs baseline: 1.8677x; 1.0016x over previous
#include <cuda_runtime.h>
#include <math.h>

#define B  4
#define NN 65536
#define KK 16
#define DD 32
#define NP 16384

// scratch
__device__ float  g_pool_t[(size_t)B * NN * DD];    // 33.6 MB  [b][n][d]
__device__ float  g_interp_t[(size_t)B * NP * DD];  //  8.4 MB  [b][np][d]
__device__ float4 g_xyz4[(size_t)B * NN];           //  4.2 MB  padded xyz

#define XB   (B * NN / 256)        // 1024  xyz padding blocks (K0)
#define TB1  (B * (NN / 32))       // 8192  transpose feat_pool tiles
#define TB2  (B * (NP / 32))       // 2048  transpose feat_interp tiles
#define RELB (B * NN * KK / 512)   // 8192  rel blocks (512 pairs each)
#define K1B  (TB1 + TB2 + RELB)    // 18432 = 9 * 2048
#define PB   (B * (NP / 32))       // 2048  pool blocks
#define IB4  (B * (NN / 128))      // 2048  interp blocks (4 tiles each)

// ============ K0: pad xyz [B*N,3] -> float4 ============
__global__ void __launch_bounds__(256) kernelX(const float* __restrict__ xyz) {
    __shared__ float s[768];
    int tid = threadIdx.x;
    int p0 = blockIdx.x * 256;
    const float* src = xyz + (size_t)p0 * 3;
    s[tid]       = __ldcs(&src[tid]);
    s[256 + tid] = __ldcs(&src[256 + tid]);
    s[512 + tid] = __ldcs(&src[512 + tid]);
    __syncthreads();
    g_xyz4[p0 + tid] = make_float4(s[tid * 3], s[tid * 3 + 1], s[tid * 3 + 2], 0.0f);
}

// ============ K1: transposes + rel, interleaved 5:4 ============
__global__ void __launch_bounds__(256) kernel1(
    const float* __restrict__ feat_pool,
    const float* __restrict__ feat_interp,
    const int*   __restrict__ nidx,
    float* __restrict__ out_rel)
{
    __shared__ float smem[5120];   // 20 KB
    int bid = blockIdx.x;
    int tid = threadIdx.x;
    int r = bid % 9;
    int g = bid / 9;

    if (r < 5) {
        // -------- transpose [B,32,M] -> [B,M,32] --------
        float (*tile)[33] = (float (*)[33])smem;
        int tb = g * 5 + r;          // 0..10239
        const float* in;
        float* outp;
        int M;
        if (tb < TB1) { in = feat_pool;   outp = g_pool_t;   M = NN; }
        else          { in = feat_interp; outp = g_interp_t; M = NP; tb -= TB1; }
        int mb = M / 32;
        int b  = tb / mb;
        int m0 = (tb - b * mb) * 32;
        int tx = tid & 31, ty = tid >> 5;
#pragma unroll
        for (int rr = 0; rr < 4; rr++) {
            int d = ty + 8 * rr;
            tile[d][tx] = __ldcs(&in[((size_t)(b * DD + d)) * M + m0 + tx]);
        }
        __syncthreads();
#pragma unroll
        for (int rr = 0; rr < 4; rr++) {
            int m = ty + 8 * rr;
            outp[((size_t)(b * M + m0 + m)) * DD + tx] = tile[tx][m];
        }
    } else {
        // -------- rel: 512 pairs / block, 2 pairs / thread --------
        int rb = g * 4 + (r - 5);            // 0..8191
        int pbase = rb * 512 + tid * 2;      // global pair index of pair0

        int2 ii = __ldcs((const int2*)(nidx + pbase));

        int b   = pbase >> 20;               // N*K = 2^20
        int nk0 = pbase & 0xFFFFF;
        int n0  = nk0 >> 4;
        int n1  = (nk0 + 1) >> 4;
        int bb  = b << 16;

        // issue all 4 loads before use (MLP)
        float4 Q0 = __ldg(&g_xyz4[bb + ii.x]);
        float4 Q1 = __ldg(&g_xyz4[bb + ii.y]);
        float4 P0 = __ldg(&g_xyz4[bb + n0]);
        float4 P1 = __ldg(&g_xyz4[bb + n1]);

        float rx0 = P0.x - Q0.x, ry0 = P0.y - Q0.y, rz0 = P0.z - Q0.z;
        float d0 = sqrtf(rx0 * rx0 + ry0 * ry0 + rz0 * rz0);
        float rx1 = P1.x - Q1.x, ry1 = P1.y - Q1.y, rz1 = P1.z - Q1.z;
        float d1 = sqrtf(rx1 * rx1 + ry1 * ry1 + rz1 * rz1);

        float4* sp = (float4*)(smem + tid * 20);
        sp[0] = make_float4(d0, rx0, ry0, rz0);
        sp[1] = make_float4(P0.x, P0.y, P0.z, Q0.x);
        sp[2] = make_float4(Q0.y, Q0.z, d1, rx1);
        sp[3] = make_float4(ry1, rz1, P1.x, P1.y);
        sp[4] = make_float4(P1.z, Q1.x, Q1.y, Q1.z);
        __syncthreads();

        float4* o4       = (float4*)(out_rel + (size_t)rb * 5120);
        const float4* s4 = (const float4*)smem;
#pragma unroll
        for (int j = 0; j < 5; j++)
            __stcs(&o4[j * 256 + tid], s4[j * 256 + tid]);
    }
}

// ============ K2: pool + interp ============
__global__ void __launch_bounds__(256) kernel2(
    const int* __restrict__ pool_idx,
    const int* __restrict__ interp_idx,
    float* __restrict__ out_pool,
    float* __restrict__ out_interp)
{
    __shared__ float smem[4 * 32 * 33];
    int bid = blockIdx.x;
    int tid = threadIdx.x;
    int lane = tid & 31, w = tid >> 5;
    int row  = w * 4 + (lane >> 3);
    int dv   = lane & 7;
    int r = bid & 1;
    int g = bid >> 1;

    if (r == 0) {
        // -------- gather-max pooling --------
        float (*tile)[33] = (float (*)[33])smem;
        int b   = g / (NP / 32);
        int np0 = (g - b * (NP / 32)) * 32;
        const int* ip = pool_idx + (b * NP + np0 + row) * KK;
        const float* basep = g_pool_t + (size_t)b * NN * DD;

        float4 m = make_float4(-INFINITY, -INFINITY, -INFINITY, -INFINITY);
#pragma unroll
        for (int kc = 0; kc < 4; kc++) {
            int4 q = __ldcs((const int4*)ip + kc);
            int qq[4] = {q.x, q.y, q.z, q.w};
#pragma unroll
            for (int j = 0; j < 4; j++) {
                float4 v = *(const float4*)(basep + qq[j] * DD + dv * 4);
                m.x = fmaxf(m.x, v.x); m.y = fmaxf(m.y, v.y);
                m.z = fmaxf(m.z, v.z); m.w = fmaxf(m.w, v.w);
            }
        }
        tile[row][dv * 4 + 0] = m.x;
        tile[row][dv * 4 + 1] = m.y;
        tile[row][dv * 4 + 2] = m.z;
        tile[row][dv * 4 + 3] = m.w;
        __syncthreads();
#pragma unroll
        for (int rr = 0; rr < 4; rr++) {
            int d = w + 8 * rr;
            __stcs(&out_pool[(size_t)(b * DD + d) * NP + np0 + lane], tile[lane][d]);
        }
    } else {
        // -------- nearest interpolation: 4 tiles / block --------
        float (*tile)[33] = (float (*)[33])smem;
        int b  = g / (NN / 128);
        int u0 = (g - b * (NN / 128)) * 128;

        float4 v[4];
#pragma unroll
        for (int it = 0; it < 4; it++) {
            int i = __ldg(&interp_idx[b * NN + u0 + it * 32 + row]);
            v[it] = *(const float4*)(g_interp_t + ((size_t)(b * NP + i)) * DD + dv * 4);
        }
#pragma unroll
        for (int it = 0; it < 4; it++) {
            tile[it * 32 + row][dv * 4 + 0] = v[it].x;
            tile[it * 32 + row][dv * 4 + 1] = v[it].y;
            tile[it * 32 + row][dv * 4 + 2] = v[it].z;
            tile[it * 32 + row][dv * 4 + 3] = v[it].w;
        }
        __syncthreads();
#pragma unroll
        for (int it = 0; it < 4; it++) {
#pragma unroll
            for (int rr = 0; rr < 4; rr++) {
                int d = w + 8 * rr;
                __stcs(&out_interp[(size_t)(b * DD + d) * NN + u0 + it * 32 + lane],
                       tile[it * 32 + lane][d]);
            }
        }
    }
}

extern "C" void kernel_launch(void* const* d_in, const int* in_sizes, int n_in,
                              void* d_out, int out_size) {
    const float* xyz         = (const float*)d_in[0];   // [B,N,3]
    const int*   neigh_idx   = (const int*)  d_in[1];   // [B,N,K]
    const float* feat_pool   = (const float*)d_in[2];   // [B,32,N,1]
    const int*   pool_idx    = (const int*)  d_in[3];   // [B,Np,K]
    const float* feat_interp = (const float*)d_in[4];   // [B,32,Np,1]
    const int*   interp_idx  = (const int*)  d_in[5];   // [B,N,1]

    float* out = (float*)d_out;
    float* out_rel    = out;                                // B*N*K*10
    float* out_pool   = out + (size_t)B * NN * KK * 10;     // B*32*Np
    float* out_interp = out_pool + (size_t)B * DD * NP;     // B*32*N

    kernelX<<<XB, 256>>>(xyz);
    kernel1<<<K1B, 256>>>(feat_pool, feat_interp, neigh_idx, out_rel);
    kernel2<<<PB + IB4, 256>>>(pool_idx, interp_idx, out_pool, out_interp);
}

// round 7
// speedup vs baseline: 1.8824x; 1.0079x over previous
#include <cuda_runtime.h>
#include <math.h>

#define B  4
#define NN 65536
#define KK 16
#define DD 32
#define NP 16384

// scratch
__device__ float  g_pool_t[(size_t)B * NN * DD];    // 33.6 MB  [b][n][d]
__device__ float  g_interp_t[(size_t)B * NP * DD];  //  8.4 MB  [b][np][d]
__device__ float4 g_xyz4[(size_t)B * NN];           //  4.2 MB  padded xyz

#define TB1  (B * (NN / 32))       // 8192  transpose feat_pool tiles
#define TB2  (B * (NP / 32))       // 2048  transpose feat_interp tiles
#define XB   (B * NN / 256)        // 1024  xyz padding blocks
#define K0B  (TB1 + TB2 + XB)      // 11264

#define RELB (B * NN * KK / 1024)  // 4096  rel blocks (1024 pairs each)
#define POOLB (B * (NP / 32))      // 2048  pool blocks
#define IB4  (B * (NN / 128))      // 2048  interp blocks (4 tiles each)
#define K1B  (RELB + POOLB + IB4)  // 8192, dispatched bid&3

// ============ K0: xyz padding + both transposes ============
__global__ void __launch_bounds__(256) kernel0(
    const float* __restrict__ xyz,
    const float* __restrict__ feat_pool,
    const float* __restrict__ feat_interp)
{
    __shared__ float sm[32 * 33];
    int bid = blockIdx.x;
    int tid = threadIdx.x;

    if (bid < XB) {
        // pad xyz [B*N,3] -> [B*N] float4
        float* s = sm;   // needs 768 floats
        int p0 = bid * 256;
        const float* src = xyz + (size_t)p0 * 3;
        s[tid]       = __ldcs(&src[tid]);
        s[256 + tid] = __ldcs(&src[256 + tid]);
        s[512 + tid] = __ldcs(&src[512 + tid]);
        __syncthreads();
        g_xyz4[p0 + tid] = make_float4(s[tid * 3], s[tid * 3 + 1], s[tid * 3 + 2], 0.0f);
    } else {
        // transpose [B,32,M] -> [B,M,32]
        float (*tile)[33] = (float (*)[33])sm;
        int tb = bid - XB;
        const float* in;
        float* outp;
        int M;
        if (tb < TB1) { in = feat_pool;   outp = g_pool_t;   M = NN; }
        else          { in = feat_interp; outp = g_interp_t; M = NP; tb -= TB1; }
        int mb = M / 32;
        int b  = tb / mb;
        int m0 = (tb - b * mb) * 32;
        int tx = tid & 31, ty = tid >> 5;
#pragma unroll
        for (int rr = 0; rr < 4; rr++) {
            int d = ty + 8 * rr;
            tile[d][tx] = __ldcs(&in[((size_t)(b * DD + d)) * M + m0 + tx]);
        }
        __syncthreads();
#pragma unroll
        for (int rr = 0; rr < 4; rr++) {
            int m = ty + 8 * rr;
            outp[((size_t)(b * M + m0 + m)) * DD + tx] = tile[tx][m];
        }
    }
}

// stage one pair-couple (P, Q0, Q1) -> 20 floats at smem[tid*20]
__device__ __forceinline__ void stage_rel(float* smem, int tid,
                                          float4 P, float4 Q0, float4 Q1) {
    float rx0 = P.x - Q0.x, ry0 = P.y - Q0.y, rz0 = P.z - Q0.z;
    float d0 = sqrtf(rx0 * rx0 + ry0 * ry0 + rz0 * rz0);
    float rx1 = P.x - Q1.x, ry1 = P.y - Q1.y, rz1 = P.z - Q1.z;
    float d1 = sqrtf(rx1 * rx1 + ry1 * ry1 + rz1 * rz1);
    float4* sp = (float4*)(smem + tid * 20);
    sp[0] = make_float4(d0, rx0, ry0, rz0);
    sp[1] = make_float4(P.x, P.y, P.z, Q0.x);
    sp[2] = make_float4(Q0.y, Q0.z, d1, rx1);
    sp[3] = make_float4(ry1, rz1, P.x, P.y);
    sp[4] = make_float4(P.z, Q1.x, Q1.y, Q1.z);
}

// ============ K1: rel + pool + interp, interleaved (bid&3) ============
__global__ void __launch_bounds__(256) kernel1(
    const int* __restrict__ nidx,
    const int* __restrict__ pool_idx,
    const int* __restrict__ interp_idx,
    float* __restrict__ out_rel,
    float* __restrict__ out_pool,
    float* __restrict__ out_interp)
{
    __shared__ float smem[5120];   // 20 KB
    int bid = blockIdx.x;
    int tid = threadIdx.x;
    int r = bid & 3;
    int g = bid >> 2;

    if (r == 0) {
        // -------- gather-max pooling --------
        float (*tile)[33] = (float (*)[33])smem;
        int lane = tid & 31, w = tid >> 5;
        int row  = w * 4 + (lane >> 3);
        int dv   = lane & 7;
        int b   = g / (NP / 32);
        int np0 = (g - b * (NP / 32)) * 32;
        const int* ip = pool_idx + (b * NP + np0 + row) * KK;
        const float* basep = g_pool_t + (size_t)b * NN * DD;

        float4 m = make_float4(-INFINITY, -INFINITY, -INFINITY, -INFINITY);
#pragma unroll
        for (int kc = 0; kc < 4; kc++) {
            int4 q = __ldcs((const int4*)ip + kc);
            int qq[4] = {q.x, q.y, q.z, q.w};
#pragma unroll
            for (int j = 0; j < 4; j++) {
                float4 v = *(const float4*)(basep + qq[j] * DD + dv * 4);
                m.x = fmaxf(m.x, v.x); m.y = fmaxf(m.y, v.y);
                m.z = fmaxf(m.z, v.z); m.w = fmaxf(m.w, v.w);
            }
        }
        tile[row][dv * 4 + 0] = m.x;
        tile[row][dv * 4 + 1] = m.y;
        tile[row][dv * 4 + 2] = m.z;
        tile[row][dv * 4 + 3] = m.w;
        __syncthreads();
#pragma unroll
        for (int rr = 0; rr < 4; rr++) {
            int d = w + 8 * rr;
            __stcs(&out_pool[(size_t)(b * DD + d) * NP + np0 + lane], tile[lane][d]);
        }
    } else if (r == 2) {
        // -------- nearest interpolation: 4 tiles / block --------
        float (*tile)[33] = (float (*)[33])smem;
        int lane = tid & 31, w = tid >> 5;
        int row  = w * 4 + (lane >> 3);
        int dv   = lane & 7;
        int b  = g / (NN / 128);
        int u0 = (g - b * (NN / 128)) * 128;

        float4 v[4];
#pragma unroll
        for (int it = 0; it < 4; it++) {
            int i = __ldg(&interp_idx[b * NN + u0 + it * 32 + row]);
            v[it] = *(const float4*)(g_interp_t + ((size_t)(b * NP + i)) * DD + dv * 4);
        }
#pragma unroll
        for (int it = 0; it < 4; it++) {
            tile[it * 32 + row][dv * 4 + 0] = v[it].x;
            tile[it * 32 + row][dv * 4 + 1] = v[it].y;
            tile[it * 32 + row][dv * 4 + 2] = v[it].z;
            tile[it * 32 + row][dv * 4 + 3] = v[it].w;
        }
        __syncthreads();
#pragma unroll
        for (int it = 0; it < 4; it++) {
#pragma unroll
            for (int rr = 0; rr < 4; rr++) {
                int d = w + 8 * rr;
                __stcs(&out_interp[(size_t)(b * DD + d) * NN + u0 + it * 32 + lane],
                       tile[it * 32 + lane][d]);
            }
        }
    } else {
        // -------- rel: 1024 pairs / block, 4 pairs / thread, 2 phases --------
        int rb = g * 2 + (r >> 1);          // r==1 -> 2g, r==3 -> 2g+1; 0..4095
        int pbase = rb * 1024;
        int b   = pbase >> 20;              // N*K = 2^20
        int bb  = b << 16;
        int nkb = pbase & 0xFFFFF;
        int t2  = tid * 2;

        // issue ALL latency-critical loads up front (MLP = 8)
        int2 iA = __ldcs((const int2*)(nidx + pbase + t2));
        int2 iB = __ldcs((const int2*)(nidx + pbase + 512 + t2));
        float4 QA0 = __ldg(&g_xyz4[bb + iA.x]);
        float4 QA1 = __ldg(&g_xyz4[bb + iA.y]);
        float4 QB0 = __ldg(&g_xyz4[bb + iB.x]);
        float4 QB1 = __ldg(&g_xyz4[bb + iB.y]);
        // pairs (2t, 2t+1) always share n since t2 is even
        float4 Pa  = __ldg(&g_xyz4[bb + ((nkb + t2) >> 4)]);
        float4 Pb  = __ldg(&g_xyz4[bb + ((nkb + 512 + t2) >> 4)]);

        float4* o4       = (float4*)(out_rel + (size_t)rb * 10240);
        const float4* s4 = (const float4*)smem;

        // phase A: pairs [pbase, pbase+512)
        stage_rel(smem, tid, Pa, QA0, QA1);
        __syncthreads();
#pragma unroll
        for (int j = 0; j < 5; j++)
            __stcs(&o4[j * 256 + tid], s4[j * 256 + tid]);
        __syncthreads();

        // phase B: pairs [pbase+512, pbase+1024)
        stage_rel(smem, tid, Pb, QB0, QB1);
        __syncthreads();
#pragma unroll
        for (int j = 0; j < 5; j++)
            __stcs(&o4[1280 + j * 256 + tid], s4[j * 256 + tid]);
    }
}

extern "C" void kernel_launch(void* const* d_in, const int* in_sizes, int n_in,
                              void* d_out, int out_size) {
    const float* xyz         = (const float*)d_in[0];   // [B,N,3]
    const int*   neigh_idx   = (const int*)  d_in[1];   // [B,N,K]
    const float* feat_pool   = (const float*)d_in[2];   // [B,32,N,1]
    const int*   pool_idx    = (const int*)  d_in[3];   // [B,Np,K]
    const float* feat_interp = (const float*)d_in[4];   // [B,32,Np,1]
    const int*   interp_idx  = (const int*)  d_in[5];   // [B,N,1]

    float* out = (float*)d_out;
    float* out_rel    = out;                                // B*N*K*10
    float* out_pool   = out + (size_t)B * NN * KK * 10;     // B*32*Np
    float* out_interp = out_pool + (size_t)B * DD * NP;     // B*32*N

    kernel0<<<K0B, 256>>>(xyz, feat_pool, feat_interp);
    kernel1<<<K1B, 256>>>(neigh_idx, pool_idx, interp_idx,
                          out_rel, out_pool, out_interp);
}

// round 8
// speedup vs baseline: 1.9190x; 1.0194x over previous
#include <cuda_runtime.h>
#include <math.h>
#include <stdint.h>

#define B  4
#define NN 65536
#define KK 16
#define DD 32
#define NP 16384

// scratch
__device__ float  g_pool_t[(size_t)B * NN * DD];    // 33.6 MB  [b][n][d]
__device__ float  g_interp_t[(size_t)B * NP * DD];  //  8.4 MB  [b][np][d]
__device__ float4 g_xyz4[(size_t)B * NN];           //  4.2 MB  padded xyz

#define TB1  (B * (NN / 32))       // 8192  transpose feat_pool tiles
#define TB2  (B * (NP / 32))       // 2048  transpose feat_interp tiles
#define XB   (B * NN / 256)        // 1024  xyz padding blocks
#define K0B  (TB1 + TB2 + XB)      // 11264

#define RELB  (B * NN * KK / 512)  // 8192  rel blocks (512 pairs each)
#define POOLB (B * (NP / 32))      // 2048  pool blocks
#define IB4   (B * (NN / 128))     // 2048  interp blocks (4 tiles each)
#define K1B   (RELB + POOLB + IB4) // 12288, dispatched bid%6 (rel gets 4/6)

__device__ __forceinline__ uint32_t smem_u32(const void* p) {
    uint32_t a;
    asm("{ .reg .u64 t; cvta.to.shared.u64 t, %1; cvt.u32.u64 %0, t; }"
        : "=r"(a) : "l"(p));
    return a;
}

// ============ K0: xyz padding + both transposes ============
__global__ void __launch_bounds__(256) kernel0(
    const float* __restrict__ xyz,
    const float* __restrict__ feat_pool,
    const float* __restrict__ feat_interp)
{
    __shared__ float sm[32 * 33];
    int bid = blockIdx.x;
    int tid = threadIdx.x;

    if (bid < XB) {
        // pad xyz [B*N,3] -> [B*N] float4
        float* s = sm;   // needs 768 floats
        int p0 = bid * 256;
        const float* src = xyz + (size_t)p0 * 3;
        s[tid]       = __ldcs(&src[tid]);
        s[256 + tid] = __ldcs(&src[256 + tid]);
        s[512 + tid] = __ldcs(&src[512 + tid]);
        __syncthreads();
        g_xyz4[p0 + tid] = make_float4(s[tid * 3], s[tid * 3 + 1], s[tid * 3 + 2], 0.0f);
    } else {
        // transpose [B,32,M] -> [B,M,32]
        float (*tile)[33] = (float (*)[33])sm;
        int tb = bid - XB;
        const float* in;
        float* outp;
        int M;
        if (tb < TB1) { in = feat_pool;   outp = g_pool_t;   M = NN; }
        else          { in = feat_interp; outp = g_interp_t; M = NP; tb -= TB1; }
        int mb = M / 32;
        int b  = tb / mb;
        int m0 = (tb - b * mb) * 32;
        int tx = tid & 31, ty = tid >> 5;
#pragma unroll
        for (int rr = 0; rr < 4; rr++) {
            int d = ty + 8 * rr;
            tile[d][tx] = __ldcs(&in[((size_t)(b * DD + d)) * M + m0 + tx]);
        }
        __syncthreads();
#pragma unroll
        for (int rr = 0; rr < 4; rr++) {
            int m = ty + 8 * rr;
            outp[((size_t)(b * M + m0 + m)) * DD + tx] = tile[tx][m];
        }
    }
}

// ============ K1: rel (TMA bulk store) + pool + interp, bid%6 ============
__global__ void __launch_bounds__(256) kernel1(
    const int* __restrict__ nidx,
    const int* __restrict__ pool_idx,
    const int* __restrict__ interp_idx,
    float* __restrict__ out_rel,
    float* __restrict__ out_pool,
    float* __restrict__ out_interp)
{
    __shared__ __align__(16) float smem[5120];   // 20 KB
    int bid = blockIdx.x;
    int tid = threadIdx.x;
    int r = bid % 6;
    int g = bid / 6;

    if (r == 0) {
        // -------- gather-max pooling --------
        float (*tile)[33] = (float (*)[33])smem;
        int lane = tid & 31, w = tid >> 5;
        int row  = w * 4 + (lane >> 3);
        int dv   = lane & 7;
        int b   = g / (NP / 32);
        int np0 = (g - b * (NP / 32)) * 32;
        const int* ip = pool_idx + (b * NP + np0 + row) * KK;
        const float* basep = g_pool_t + (size_t)b * NN * DD;

        float4 m = make_float4(-INFINITY, -INFINITY, -INFINITY, -INFINITY);
#pragma unroll
        for (int kc = 0; kc < 4; kc++) {
            int4 q = __ldcs((const int4*)ip + kc);
            int qq[4] = {q.x, q.y, q.z, q.w};
#pragma unroll
            for (int j = 0; j < 4; j++) {
                float4 v = *(const float4*)(basep + qq[j] * DD + dv * 4);
                m.x = fmaxf(m.x, v.x); m.y = fmaxf(m.y, v.y);
                m.z = fmaxf(m.z, v.z); m.w = fmaxf(m.w, v.w);
            }
        }
        tile[row][dv * 4 + 0] = m.x;
        tile[row][dv * 4 + 1] = m.y;
        tile[row][dv * 4 + 2] = m.z;
        tile[row][dv * 4 + 3] = m.w;
        __syncthreads();
#pragma unroll
        for (int rr = 0; rr < 4; rr++) {
            int d = w + 8 * rr;
            __stcs(&out_pool[(size_t)(b * DD + d) * NP + np0 + lane], tile[lane][d]);
        }
    } else if (r == 3) {
        // -------- nearest interpolation: 4 tiles / block --------
        float (*tile)[33] = (float (*)[33])smem;
        int lane = tid & 31, w = tid >> 5;
        int row  = w * 4 + (lane >> 3);
        int dv   = lane & 7;
        int b  = g / (NN / 128);
        int u0 = (g - b * (NN / 128)) * 128;

        float4 v[4];
#pragma unroll
        for (int it = 0; it < 4; it++) {
            int i = __ldg(&interp_idx[b * NN + u0 + it * 32 + row]);
            v[it] = *(const float4*)(g_interp_t + ((size_t)(b * NP + i)) * DD + dv * 4);
        }
#pragma unroll
        for (int it = 0; it < 4; it++) {
            tile[it * 32 + row][dv * 4 + 0] = v[it].x;
            tile[it * 32 + row][dv * 4 + 1] = v[it].y;
            tile[it * 32 + row][dv * 4 + 2] = v[it].z;
            tile[it * 32 + row][dv * 4 + 3] = v[it].w;
        }
        __syncthreads();
#pragma unroll
        for (int it = 0; it < 4; it++) {
#pragma unroll
            for (int rr = 0; rr < 4; rr++) {
                int d = w + 8 * rr;
                __stcs(&out_interp[(size_t)(b * DD + d) * NN + u0 + it * 32 + lane],
                       tile[it * 32 + lane][d]);
            }
        }
    } else {
        // -------- rel: 512 pairs / block, 2 pairs / thread, TMA bulk store --------
        // r in {1,2,4,5} -> sub 0..3
        int sub = (r < 3) ? (r - 1) : (r - 2);
        int rb = g * 4 + sub;               // 0..8191
        int pbase = rb * 512;
        int b   = pbase >> 20;              // N*K = 2^20
        int bb  = b << 16;
        int nkb = pbase & 0xFFFFF;
        int t2  = tid * 2;

        int2 ii = __ldcs((const int2*)(nidx + pbase + t2));
        float4 Q0 = __ldg(&g_xyz4[bb + ii.x]);
        float4 Q1 = __ldg(&g_xyz4[bb + ii.y]);
        // pairs (2t, 2t+1) share n since t2 is even and K=16
        float4 P  = __ldg(&g_xyz4[bb + ((nkb + t2) >> 4)]);

        float rx0 = P.x - Q0.x, ry0 = P.y - Q0.y, rz0 = P.z - Q0.z;
        float d0 = sqrtf(rx0 * rx0 + ry0 * ry0 + rz0 * rz0);
        float rx1 = P.x - Q1.x, ry1 = P.y - Q1.y, rz1 = P.z - Q1.z;
        float d1 = sqrtf(rx1 * rx1 + ry1 * ry1 + rz1 * rz1);

        float4* sp = (float4*)(smem + tid * 20);
        sp[0] = make_float4(d0, rx0, ry0, rz0);
        sp[1] = make_float4(P.x, P.y, P.z, Q0.x);
        sp[2] = make_float4(Q0.y, Q0.z, d1, rx1);
        sp[3] = make_float4(ry1, rz1, P.x, P.y);
        sp[4] = make_float4(P.z, Q1.x, Q1.y, Q1.z);
        __syncthreads();

        // one bulk S2G copy of the whole 20 KB chunk (contiguous in out_rel)
        asm volatile("fence.proxy.async.shared::cta;" ::: "memory");
        if (tid == 0) {
            uint32_t sa = smem_u32(smem);
            float* gp = out_rel + (size_t)rb * 5120;
            asm volatile(
                "cp.async.bulk.global.shared::cta.bulk_group [%0], [%1], %2;"
                :: "l"(gp), "r"(sa), "n"(20480) : "memory");
            asm volatile("cp.async.bulk.commit_group;" ::: "memory");
            asm volatile("cp.async.bulk.wait_group.read 0;" ::: "memory");
        }
        __syncthreads();
    }
}

extern "C" void kernel_launch(void* const* d_in, const int* in_sizes, int n_in,
                              void* d_out, int out_size) {
    const float* xyz         = (const float*)d_in[0];   // [B,N,3]
    const int*   neigh_idx   = (const int*)  d_in[1];   // [B,N,K]
    const float* feat_pool   = (const float*)d_in[2];   // [B,32,N,1]
    const int*   pool_idx    = (const int*)  d_in[3];   // [B,Np,K]
    const float* feat_interp = (const float*)d_in[4];   // [B,32,Np,1]
    const int*   interp_idx  = (const int*)  d_in[5];   // [B,N,1]

    float* out = (float*)d_out;
    float* out_rel    = out;                                // B*N*K*10
    float* out_pool   = out + (size_t)B * NN * KK * 10;     // B*32*Np
    float* out_interp = out_pool + (size_t)B * DD * NP;     // B*32*N

    kernel0<<<K0B, 256>>>(xyz, feat_pool, feat_interp);
    kernel1<<<K1B, 256>>>(neigh_idx, pool_idx, interp_idx,
                          out_rel, out_pool, out_interp);
}